// round 7
// baseline (speedup 1.0000x reference)
#include <cuda_runtime.h>
#include <cuda_bf16.h>
#include <string.h>

#define BB 8192
#define NN 36
#define H 8
#define DH 9
#define ACT 10
#define GAT 72
#define NTHREADS 144   // 2 batches x 8 heads x 9 node-groups
#define LOG2E 1.4426950408889634f

// h4 layout: per head block padded to 436 floats (36 rows x 12 + 4 pad)
// -> head bank offset = hh*20 mod 32, all 8 distinct -> conflict-free LDS
#define HSTRIDE 436
#define BSTRIDE (H * HSTRIDE)   // 3488 floats per batch slot (mod 32 == 0)

// packed const buffer layout (floats)
#define C_WP   0      // W padded: 8 heads x 7 in x 12 (9 used, 3 zero)   [672]
#define C_AA   672    // interleaved (a_src*log2e, a_dst*log2e): 8 x 9 x 2 [144]
#define C_WD   816    // W_down [72]
#define C_WMU  888    // W_mu [720]
#define C_BMU  1608   // b_mu [10]
#define C_BDN  1618   // b_down [1]
#define C_SZ   1620   // total (x4 = 405 float4)

__device__ __align__(16) float gC[C_SZ];
__device__ unsigned int gMLo[NN];
__device__ unsigned int gMHi[NN];

__device__ __forceinline__ float2 ffma2(float2 a, float2 b, float2 c) {
    unsigned long long au, bu, cu, du;
    memcpy(&au, &a, 8); memcpy(&bu, &b, 8); memcpy(&cu, &c, 8);
    asm("fma.rn.f32x2 %0, %1, %2, %3;" : "=l"(du) : "l"(au), "l"(bu), "l"(cu));
    float2 d; memcpy(&d, &du, 8);
    return d;
}

__device__ __forceinline__ float2 fadd2(float2 a, float2 b) {
    unsigned long long au, bu, du;
    memcpy(&au, &a, 8); memcpy(&bu, &b, 8);
    asm("add.rn.f32x2 %0, %1, %2;" : "=l"(du) : "l"(au), "l"(bu));
    float2 d; memcpy(&d, &du, 8);
    return d;
}

__device__ __forceinline__ float2 fmul2(float2 a, float2 b) {
    unsigned long long au, bu, du;
    memcpy(&au, &a, 8); memcpy(&bu, &b, 8);
    asm("mul.rn.f32x2 %0, %1, %2;" : "=l"(du) : "l"(au), "l"(bu));
    float2 d; memcpy(&d, &du, 8);
    return d;
}

__device__ __forceinline__ float ex2_approx(float v) {
    float r;
    asm("ex2.approx.ftz.f32 %0, %1;" : "=f"(r) : "f"(v));
    return r;
}

__global__ void prep_kernel(const float* __restrict__ W,
                            const float* __restrict__ a_src,
                            const float* __restrict__ a_dst,
                            const float* __restrict__ W_down,
                            const float* __restrict__ b_down,
                            const float* __restrict__ W_mu,
                            const float* __restrict__ b_mu,
                            const int*   __restrict__ adj) {
    const int t = threadIdx.x;
    for (int i = t; i < 8 * 7 * 12; i += 288) {
        int hh = i / 84, r = (i % 84) / 12, c = i % 12;
        gC[C_WP + i] = (c < 9) ? W[hh * 63 + r * 9 + c] : 0.0f;
    }
    for (int i = t; i < 72; i += 288) {
        int hh = i / 9, d = i % 9;
        gC[C_AA + hh * 18 + d * 2 + 0] = a_src[i] * LOG2E;
        gC[C_AA + hh * 18 + d * 2 + 1] = a_dst[i] * LOG2E;
        gC[C_WD + i] = W_down[i];
    }
    for (int i = t; i < 720; i += 288) gC[C_WMU + i] = W_mu[i];
    if (t < ACT) gC[C_BMU + t] = b_mu[t];
    if (t == 0) { gC[C_BDN] = b_down[0]; gC[C_BDN + 1] = 0.0f; }
    if (t < NN) {
        unsigned lo = 0u, hi = 0u;
        for (int j = 0; j < NN; j++)
            if (adj[t * NN + j] > 0) { if (j < 32) lo |= 1u << j; else hi |= 1u << (j - 32); }
        gMLo[t] = lo; gMHi[t] = hi;
    }
}

__global__ __launch_bounds__(NTHREADS, 5) void gnn_kernel(
    const float* __restrict__ x, float* __restrict__ out) {
    __shared__ __align__(16) float cb[C_SZ];
    __shared__ __align__(16) float h4[2 * BSTRIDE];     // padded, see HSTRIDE
    __shared__ __align__(16) float xs[2][NN * 8];
    __shared__ float red[2][H * NN];
    __shared__ float feat[2][GAT];
    __shared__ unsigned int mlo[NN], mhi[NN];

    const int tid = threadIdx.x;

    // ---- Stage 0: stage packed consts + 2 x-blocks ----
    {
        const float4* src = (const float4*)gC;
        float4* dst = (float4*)cb;
        for (int i = tid; i < C_SZ / 4; i += NTHREADS) dst[i] = src[i];
        const float4* xsrc = (const float4*)(x + (size_t)blockIdx.x * 2 * (NN * 8));
        float4* xdst = (float4*)&xs[0][0];
        for (int i = tid; i < 2 * NN * 8 / 4; i += NTHREADS) xdst[i] = xsrc[i];
        if (tid < NN) { mlo[tid] = gMLo[tid]; mhi[tid] = gMHi[tid]; }
    }
    __syncthreads();

    const int bi = tid / 72;           // batch slot within CTA
    const int r  = tid % 72;
    const int hh = r / 9;              // head
    const int g  = r % 9;              // node group: nodes g, g+9, g+18, g+27

    // ---- Stage 1: h = xc @ W for 4 nodes, e in log2 domain ----
    float xc[4][7];
    #pragma unroll
    for (int q = 0; q < 4; q++) {
        const int n = g + 9 * q;
        const float4* xr = (const float4*)&xs[bi][n * 8];
        const float4 xa = xr[0], xb = xr[1];
        xc[q][0] = xa.x; xc[q][1] = xa.y; xc[q][2] = xa.z;
        xc[q][3] = xb.x; xc[q][4] = xb.y; xc[q][5] = xb.z; xc[q][6] = xb.w;
    }

    float2 hv[4][5];
    #pragma unroll
    for (int q = 0; q < 4; q++)
        #pragma unroll
        for (int k = 0; k < 5; k++) hv[q][k] = make_float2(0.f, 0.f);

    #pragma unroll
    for (int i = 0; i < 7; i++) {
        const float4* wr = (const float4*)&cb[C_WP + hh * 84 + i * 12];
        const float4 wA = wr[0], wB = wr[1], wC = wr[2];
        const float2 w01 = make_float2(wA.x, wA.y);
        const float2 w23 = make_float2(wA.z, wA.w);
        const float2 w45 = make_float2(wB.x, wB.y);
        const float2 w67 = make_float2(wB.z, wB.w);
        const float2 w8x = make_float2(wC.x, wC.y);
        #pragma unroll
        for (int q = 0; q < 4; q++) {
            const float2 xp = make_float2(xc[q][i], xc[q][i]);
            hv[q][0] = ffma2(xp, w01, hv[q][0]);
            hv[q][1] = ffma2(xp, w23, hv[q][1]);
            hv[q][2] = ffma2(xp, w45, hv[q][2]);
            hv[q][3] = ffma2(xp, w67, hv[q][3]);
            hv[q][4] = ffma2(xp, w8x, hv[q][4]);
        }
    }

    const float2* aa = (const float2*)&cb[C_AA + hh * 18];
    float2 aar[9];
    #pragma unroll
    for (int d = 0; d < 9; d++) aar[d] = aa[d];

    float e1q[4];
    #pragma unroll
    for (int q = 0; q < 4; q++) {
        float hd[9] = { hv[q][0].x, hv[q][0].y, hv[q][1].x, hv[q][1].y,
                        hv[q][2].x, hv[q][2].y, hv[q][3].x, hv[q][3].y, hv[q][4].x };
        float2 e12 = make_float2(0.f, 0.f);
        #pragma unroll
        for (int d = 0; d < 9; d++)
            e12 = ffma2(make_float2(hd[d], hd[d]), aar[d], e12);
        const int n = g + 9 * q;
        float4* hr = (float4*)&h4[bi * BSTRIDE + hh * HSTRIDE + n * 12];
        hr[0] = make_float4(hd[0], hd[1], hd[2], hd[3]);
        hr[1] = make_float4(hd[4], hd[5], hd[6], hd[7]);
        hr[2] = make_float4(hd[8], 1.0f, e12.y, 0.f);     // h8, one, ed(log2)
        e1q[q] = e12.x;
    }

    // masks for my 4 rows
    unsigned mL[4], mH[4];
    #pragma unroll
    for (int q = 0; q < 4; q++) { mL[q] = mlo[g + 9 * q]; mH[q] = mhi[g + 9 * q]; }
    __syncthreads();

    // ---- Stage 2: dense masked softmax (log2) fused with P@h, 4 rows/thread ----
    const float4* __restrict__ hb4 =
        (const float4*)&h4[bi * BSTRIDE + hh * HSTRIDE];

    float2 a0[4], a1[4], a2[4], a3[4], a4s[4];
    #pragma unroll
    for (int q = 0; q < 4; q++) {
        a0[q] = make_float2(0.f, 0.f); a1[q] = a0[q]; a2[q] = a0[q];
        a3[q] = a0[q]; a4s[q] = a0[q];
    }

    const float2 e01 = make_float2(e1q[0], e1q[1]);
    const float2 e23 = make_float2(e1q[2], e1q[3]);
    const float2 k02 = make_float2(0.2f, 0.2f);

    #pragma unroll
    for (int j = 0; j < NN; j++) {
        const float4 A  = hb4[j * 3 + 0];
        const float4 Bv = hb4[j * 3 + 1];
        const float4 C  = hb4[j * 3 + 2];
        const float2 h01 = make_float2(A.x, A.y);
        const float2 h23 = make_float2(A.z, A.w);
        const float2 h45 = make_float2(Bv.x, Bv.y);
        const float2 h67 = make_float2(Bv.z, Bv.w);
        const float2 h8o = make_float2(C.x, C.y);         // (h8, 1.0)
        const float2 edj = make_float2(C.z, C.z);

        // packed v = e1 + ed, packed 0.2*v; scalar max + mask-select + ex2
        const float2 v01 = fadd2(e01, edj);
        const float2 v23 = fadd2(e23, edj);
        const float2 w01 = fmul2(v01, k02);
        const float2 w23 = fmul2(v23, k02);
        float vq[4] = { fmaxf(v01.x, w01.x), fmaxf(v01.y, w01.y),
                        fmaxf(v23.x, w23.x), fmaxf(v23.y, w23.y) };

        #pragma unroll
        for (int q = 0; q < 4; q++) {
            const unsigned bit = (j < 32) ? (mL[q] & (1u << j)) : (mH[q] & (1u << (j - 32)));
            const float p = ex2_approx(bit ? vq[q] : -1000.0f);
            const float2 pp = make_float2(p, p);
            a0[q]  = ffma2(pp, h01, a0[q]);
            a1[q]  = ffma2(pp, h23, a1[q]);
            a2[q]  = ffma2(pp, h45, a2[q]);
            a3[q]  = ffma2(pp, h67, a3[q]);
            a4s[q] = ffma2(pp, h8o, a4s[q]);              // (acc8, s)
        }
    }

    // ---- Stage 3: elu + W_down partial ----
    float wd[9];
    #pragma unroll
    for (int d = 0; d < 9; d++) wd[d] = cb[C_WD + hh * 9 + d];
    #pragma unroll
    for (int q = 0; q < 4; q++) {
        const float inv = __fdividef(1.0f, a4s[q].y);
        float od[9] = { a0[q].x, a0[q].y, a1[q].x, a1[q].y,
                        a2[q].x, a2[q].y, a3[q].x, a3[q].y, a4s[q].x };
        float pd = 0.f;
        #pragma unroll
        for (int d = 0; d < 9; d++) {
            float o = od[d] * inv;
            o = (o > 0.f) ? o : (__expf(o) - 1.0f);
            pd = fmaf(o, wd[d], pd);
        }
        red[bi][hh * NN + g + 9 * q] = pd;
    }
    __syncthreads();

    // ---- Stage 4: down-sum + feat = leaky_relu([down, t], 0.01) ----
    if (r < NN) {
        float dsum = cb[C_BDN];
        #pragma unroll
        for (int h2 = 0; h2 < H; h2++) dsum += red[bi][h2 * NN + r];
        feat[bi][r] = (dsum > 0.f) ? dsum : 0.01f * dsum;
        const float tt = xs[bi][r * 8 + 4];
        feat[bi][NN + r] = (tt > 0.f) ? tt : 0.01f * tt;
    }
    __syncthreads();

    // ---- Stage 5: mu = feat @ W_mu + b_mu ----
    // 40 lanes per batch: (a = r>>2 in 0..9) x (c = r&3 k-chunks of 18)
    if (r < 40) {
        const int a = r >> 2, c = r & 3;
        float partial = 0.f;
        #pragma unroll
        for (int k = 0; k < 18; k++) {
            const int kk = c * 18 + k;
            partial = fmaf(feat[bi][kk], cb[C_WMU + kk * ACT + a], partial);
        }
        red[bi][r] = partial;   // slot a*4 + c
    }
    __syncthreads();
    if (r < ACT) {
        float mm = cb[C_BMU + r];
        #pragma unroll
        for (int c = 0; c < 4; c++) mm += red[bi][r * 4 + c];
        out[((size_t)blockIdx.x * 2 + bi) * ACT + r] = mm;
    }
}

extern "C" void kernel_launch(void* const* d_in, const int* in_sizes, int n_in,
                              void* d_out, int out_size) {
    const float* x      = (const float*)d_in[0];
    const int*   adj    = (const int*)  d_in[1];
    const float* W      = (const float*)d_in[2];
    const float* a_src  = (const float*)d_in[3];
    const float* a_dst  = (const float*)d_in[4];
    const float* W_down = (const float*)d_in[5];
    const float* b_down = (const float*)d_in[6];
    const float* W_mu   = (const float*)d_in[7];
    const float* b_mu   = (const float*)d_in[8];
    float* out = (float*)d_out;

    prep_kernel<<<1, 288>>>(W, a_src, a_dst, W_down, b_down, W_mu, b_mu, adj);
    gnn_kernel<<<BB / 2, NTHREADS>>>(x, out);
}

// round 8
// speedup vs baseline: 1.7144x; 1.7144x over previous
#include <cuda_runtime.h>
#include <cuda_bf16.h>
#include <string.h>

#define BB 8192
#define NN 36
#define H 8
#define DH 9
#define ACT 10
#define GAT 72
#define NTHREADS 144   // 2 batches x 8 heads x 9 node-groups
#define LOG2E 1.4426950408889634f

// h4 layout: per head block padded to 436 floats (36 rows x 12 + 4 pad)
// -> head bank offset = hh*20 mod 32, all 8 distinct -> conflict-free LDS
#define HSTRIDE 436
#define BSTRIDE (H * HSTRIDE)   // 3488 floats per batch slot (mod 32 == 0)

// packed const buffer layout (floats)
#define C_WP   0      // W padded: 8 heads x 7 in x 12 (9 used, 3 zero)   [672]
#define C_AA   672    // interleaved (a_src*log2e, a_dst*log2e): 8 x 9 x 2 [144]
#define C_WD   816    // W_down [72]
#define C_WMU  888    // W_mu [720]
#define C_BMU  1608   // b_mu [10]
#define C_BDN  1618   // b_down [1]
#define C_SZ   1620   // total (x4 = 405 float4)

__device__ __align__(16) float gC[C_SZ];
__device__ unsigned int gMLo[NN];
__device__ unsigned int gMHi[NN];

__device__ __forceinline__ float2 ffma2(float2 a, float2 b, float2 c) {
    unsigned long long au, bu, cu, du;
    memcpy(&au, &a, 8); memcpy(&bu, &b, 8); memcpy(&cu, &c, 8);
    asm("fma.rn.f32x2 %0, %1, %2, %3;" : "=l"(du) : "l"(au), "l"(bu), "l"(cu));
    float2 d; memcpy(&d, &du, 8);
    return d;
}

__device__ __forceinline__ float2 fadd2(float2 a, float2 b) {
    unsigned long long au, bu, du;
    memcpy(&au, &a, 8); memcpy(&bu, &b, 8);
    asm("add.rn.f32x2 %0, %1, %2;" : "=l"(du) : "l"(au), "l"(bu));
    float2 d; memcpy(&d, &du, 8);
    return d;
}

__device__ __forceinline__ float2 fmul2(float2 a, float2 b) {
    unsigned long long au, bu, du;
    memcpy(&au, &a, 8); memcpy(&bu, &b, 8);
    asm("mul.rn.f32x2 %0, %1, %2;" : "=l"(du) : "l"(au), "l"(bu));
    float2 d; memcpy(&d, &du, 8);
    return d;
}

__device__ __forceinline__ float ex2_approx(float v) {
    float r;
    asm("ex2.approx.ftz.f32 %0, %1;" : "=f"(r) : "f"(v));
    return r;
}

__global__ void prep_kernel(const float* __restrict__ W,
                            const float* __restrict__ a_src,
                            const float* __restrict__ a_dst,
                            const float* __restrict__ W_down,
                            const float* __restrict__ b_down,
                            const float* __restrict__ W_mu,
                            const float* __restrict__ b_mu,
                            const int*   __restrict__ adj) {
    const int t = threadIdx.x;
    for (int i = t; i < 8 * 7 * 12; i += 288) {
        int hh = i / 84, r = (i % 84) / 12, c = i % 12;
        gC[C_WP + i] = (c < 9) ? W[hh * 63 + r * 9 + c] : 0.0f;
    }
    for (int i = t; i < 72; i += 288) {
        int hh = i / 9, d = i % 9;
        gC[C_AA + hh * 18 + d * 2 + 0] = a_src[i] * LOG2E;
        gC[C_AA + hh * 18 + d * 2 + 1] = a_dst[i] * LOG2E;
        gC[C_WD + i] = W_down[i];
    }
    for (int i = t; i < 720; i += 288) gC[C_WMU + i] = W_mu[i];
    if (t < ACT) gC[C_BMU + t] = b_mu[t];
    if (t == 0) { gC[C_BDN] = b_down[0]; gC[C_BDN + 1] = 0.0f; }
    if (t < NN) {
        unsigned lo = 0u, hi = 0u;
        for (int j = 0; j < NN; j++)
            if (adj[t * NN + j] > 0) { if (j < 32) lo |= 1u << j; else hi |= 1u << (j - 32); }
        gMLo[t] = lo; gMHi[t] = hi;
    }
}

__global__ __launch_bounds__(NTHREADS, 4) void gnn_kernel(
    const float* __restrict__ x, float* __restrict__ out) {
    __shared__ __align__(16) float cb[C_SZ];
    __shared__ __align__(16) float h4[2 * BSTRIDE];     // padded, see HSTRIDE
    __shared__ __align__(16) float xs[2][NN * 8];
    __shared__ float red[2][H * NN];
    __shared__ float feat[2][GAT];
    __shared__ unsigned int mlo[NN], mhi[NN];

    const int tid = threadIdx.x;

    // ---- Stage 0: stage packed consts + 2 x-blocks ----
    {
        const float4* src = (const float4*)gC;
        float4* dst = (float4*)cb;
        for (int i = tid; i < C_SZ / 4; i += NTHREADS) dst[i] = src[i];
        const float4* xsrc = (const float4*)(x + (size_t)blockIdx.x * 2 * (NN * 8));
        float4* xdst = (float4*)&xs[0][0];
        for (int i = tid; i < 2 * NN * 8 / 4; i += NTHREADS) xdst[i] = xsrc[i];
        if (tid < NN) { mlo[tid] = gMLo[tid]; mhi[tid] = gMHi[tid]; }
    }
    __syncthreads();

    const int bi = tid / 72;           // batch slot within CTA
    const int r  = tid % 72;
    const int hh = r / 9;              // head
    const int g  = r % 9;              // node group: nodes g, g+9, g+18, g+27

    // ---- Stage 1: h = xc @ W for 4 nodes, e in log2 domain ----
    float xc[4][7];
    #pragma unroll
    for (int q = 0; q < 4; q++) {
        const int n = g + 9 * q;
        const float4* xr = (const float4*)&xs[bi][n * 8];
        const float4 xa = xr[0], xb = xr[1];
        xc[q][0] = xa.x; xc[q][1] = xa.y; xc[q][2] = xa.z;
        xc[q][3] = xb.x; xc[q][4] = xb.y; xc[q][5] = xb.z; xc[q][6] = xb.w;
    }

    float2 hv[4][5];
    #pragma unroll
    for (int q = 0; q < 4; q++)
        #pragma unroll
        for (int k = 0; k < 5; k++) hv[q][k] = make_float2(0.f, 0.f);

    #pragma unroll
    for (int i = 0; i < 7; i++) {
        const float4* wr = (const float4*)&cb[C_WP + hh * 84 + i * 12];
        const float4 wA = wr[0], wB = wr[1], wC = wr[2];
        const float2 w01 = make_float2(wA.x, wA.y);
        const float2 w23 = make_float2(wA.z, wA.w);
        const float2 w45 = make_float2(wB.x, wB.y);
        const float2 w67 = make_float2(wB.z, wB.w);
        const float2 w8x = make_float2(wC.x, wC.y);
        #pragma unroll
        for (int q = 0; q < 4; q++) {
            const float2 xp = make_float2(xc[q][i], xc[q][i]);
            hv[q][0] = ffma2(xp, w01, hv[q][0]);
            hv[q][1] = ffma2(xp, w23, hv[q][1]);
            hv[q][2] = ffma2(xp, w45, hv[q][2]);
            hv[q][3] = ffma2(xp, w67, hv[q][3]);
            hv[q][4] = ffma2(xp, w8x, hv[q][4]);
        }
    }

    const float2* aa = (const float2*)&cb[C_AA + hh * 18];
    float2 aar[9];
    #pragma unroll
    for (int d = 0; d < 9; d++) aar[d] = aa[d];

    float e1q[4];
    #pragma unroll
    for (int q = 0; q < 4; q++) {
        float hd[9] = { hv[q][0].x, hv[q][0].y, hv[q][1].x, hv[q][1].y,
                        hv[q][2].x, hv[q][2].y, hv[q][3].x, hv[q][3].y, hv[q][4].x };
        float2 e12 = make_float2(0.f, 0.f);
        #pragma unroll
        for (int d = 0; d < 9; d++)
            e12 = ffma2(make_float2(hd[d], hd[d]), aar[d], e12);
        const int n = g + 9 * q;
        float4* hr = (float4*)&h4[bi * BSTRIDE + hh * HSTRIDE + n * 12];
        hr[0] = make_float4(hd[0], hd[1], hd[2], hd[3]);
        hr[1] = make_float4(hd[4], hd[5], hd[6], hd[7]);
        hr[2] = make_float4(hd[8], 1.0f, e12.y, 0.f);     // h8, one, ed(log2)
        e1q[q] = e12.x;
    }

    // masks for my 4 rows
    unsigned mL[4], mH[4];
    #pragma unroll
    for (int q = 0; q < 4; q++) { mL[q] = mlo[g + 9 * q]; mH[q] = mhi[g + 9 * q]; }
    __syncthreads();

    // ---- Stage 2: dense masked softmax (log2) fused with P@h, 4 rows/thread ----
    const float4* __restrict__ hb4 =
        (const float4*)&h4[bi * BSTRIDE + hh * HSTRIDE];

    float2 a0[4], a1[4], a2[4], a3[4], a4s[4];
    #pragma unroll
    for (int q = 0; q < 4; q++) {
        a0[q] = make_float2(0.f, 0.f); a1[q] = a0[q]; a2[q] = a0[q];
        a3[q] = a0[q]; a4s[q] = a0[q];
    }

    const float2 e01 = make_float2(e1q[0], e1q[1]);
    const float2 e23 = make_float2(e1q[2], e1q[3]);
    const float2 k02 = make_float2(0.2f, 0.2f);

    #pragma unroll
    for (int j = 0; j < NN; j++) {
        const float4 A  = hb4[j * 3 + 0];
        const float4 Bv = hb4[j * 3 + 1];
        const float4 C  = hb4[j * 3 + 2];
        const float2 h01 = make_float2(A.x, A.y);
        const float2 h23 = make_float2(A.z, A.w);
        const float2 h45 = make_float2(Bv.x, Bv.y);
        const float2 h67 = make_float2(Bv.z, Bv.w);
        const float2 h8o = make_float2(C.x, C.y);         // (h8, 1.0)
        const float2 edj = make_float2(C.z, C.z);

        // packed v = e1 + ed, packed 0.2*v; scalar max + mask-select + ex2
        const float2 v01 = fadd2(e01, edj);
        const float2 v23 = fadd2(e23, edj);
        const float2 w01 = fmul2(v01, k02);
        const float2 w23 = fmul2(v23, k02);
        float vq[4] = { fmaxf(v01.x, w01.x), fmaxf(v01.y, w01.y),
                        fmaxf(v23.x, w23.x), fmaxf(v23.y, w23.y) };

        #pragma unroll
        for (int q = 0; q < 4; q++) {
            const unsigned bit = (j < 32) ? (mL[q] & (1u << j)) : (mH[q] & (1u << (j - 32)));
            const float p = ex2_approx(bit ? vq[q] : -1000.0f);
            const float2 pp = make_float2(p, p);
            a0[q]  = ffma2(pp, h01, a0[q]);
            a1[q]  = ffma2(pp, h23, a1[q]);
            a2[q]  = ffma2(pp, h45, a2[q]);
            a3[q]  = ffma2(pp, h67, a3[q]);
            a4s[q] = ffma2(pp, h8o, a4s[q]);              // (acc8, s)
        }
    }

    // ---- Stage 3: elu + W_down partial ----
    float wd[9];
    #pragma unroll
    for (int d = 0; d < 9; d++) wd[d] = cb[C_WD + hh * 9 + d];
    #pragma unroll
    for (int q = 0; q < 4; q++) {
        const float inv = __fdividef(1.0f, a4s[q].y);
        float od[9] = { a0[q].x, a0[q].y, a1[q].x, a1[q].y,
                        a2[q].x, a2[q].y, a3[q].x, a3[q].y, a4s[q].x };
        float pd = 0.f;
        #pragma unroll
        for (int d = 0; d < 9; d++) {
            float o = od[d] * inv;
            o = (o > 0.f) ? o : (__expf(o) - 1.0f);
            pd = fmaf(o, wd[d], pd);
        }
        red[bi][hh * NN + g + 9 * q] = pd;
    }
    __syncthreads();

    // ---- Stage 4: down-sum + feat = leaky_relu([down, t], 0.01) ----
    if (r < NN) {
        float dsum = cb[C_BDN];
        #pragma unroll
        for (int h2 = 0; h2 < H; h2++) dsum += red[bi][h2 * NN + r];
        feat[bi][r] = (dsum > 0.f) ? dsum : 0.01f * dsum;
        const float tt = xs[bi][r * 8 + 4];
        feat[bi][NN + r] = (tt > 0.f) ? tt : 0.01f * tt;
    }
    __syncthreads();

    // ---- Stage 5: mu = feat @ W_mu + b_mu ----
    // 40 lanes per batch: (a = r>>2 in 0..9) x (c = r&3 k-chunks of 18)
    if (r < 40) {
        const int a = r >> 2, c = r & 3;
        float partial = 0.f;
        #pragma unroll
        for (int k = 0; k < 18; k++) {
            const int kk = c * 18 + k;
            partial = fmaf(feat[bi][kk], cb[C_WMU + kk * ACT + a], partial);
        }
        red[bi][r] = partial;   // slot a*4 + c
    }
    __syncthreads();
    if (r < ACT) {
        float mm = cb[C_BMU + r];
        #pragma unroll
        for (int c = 0; c < 4; c++) mm += red[bi][r * 4 + c];
        out[((size_t)blockIdx.x * 2 + bi) * ACT + r] = mm;
    }
}

extern "C" void kernel_launch(void* const* d_in, const int* in_sizes, int n_in,
                              void* d_out, int out_size) {
    const float* x      = (const float*)d_in[0];
    const int*   adj    = (const int*)  d_in[1];
    const float* W      = (const float*)d_in[2];
    const float* a_src  = (const float*)d_in[3];
    const float* a_dst  = (const float*)d_in[4];
    const float* W_down = (const float*)d_in[5];
    const float* b_down = (const float*)d_in[6];
    const float* W_mu   = (const float*)d_in[7];
    const float* b_mu   = (const float*)d_in[8];
    float* out = (float*)d_out;

    prep_kernel<<<1, 288>>>(W, a_src, a_dst, W_down, b_down, W_mu, b_mu, adj);
    gnn_kernel<<<BB / 2, NTHREADS>>>(x, out);
}